// round 14
// baseline (speedup 1.0000x reference)
#include <cuda_runtime.h>

// Shapes: B=512, T=128, N=128, H=256
#define BB 512
#define TT 128
#define NN 128
#define HH 256

__device__ float g_xW[TT * BB * HH];   // [s][b][h]
__device__ float g_Hs2[TT * HH * BB];  // [s][h][b]
__device__ float g_Q[TT * BB * TT];    // [s][b][t]
__device__ float g_preT[BB * TT * NN]; // [b][t][n]

typedef unsigned long long ull;

__device__ __forceinline__ ull pack2(float x, float y) {
    ull r; asm("mov.b64 %0, {%1, %2};" : "=l"(r) : "f"(x), "f"(y)); return r;
}
__device__ __forceinline__ ull dup2(float x) {
    ull r; asm("mov.b64 %0, {%1, %1};" : "=l"(r) : "f"(x)); return r;
}
__device__ __forceinline__ ull ffma2(ull a, ull b, ull c) {
    ull d; asm("fma.rn.f32x2 %0, %1, %2, %3;" : "=l"(d) : "l"(a), "l"(b), "l"(c)); return d;
}
__device__ __forceinline__ ull fadd2(ull a, ull b) {
    ull d; asm("add.rn.f32x2 %0, %1, %2;" : "=l"(d) : "l"(a), "l"(b)); return d;
}
__device__ __forceinline__ void unpk(ull p, float& x, float& y) {
    asm("mov.b64 {%0, %1}, %2;" : "=f"(x), "=f"(y) : "l"(p));
}
union F4U { float4 v; ull u[2]; };

__device__ __forceinline__ float tanh_fast(float x) {
    float y; asm("tanh.approx.f32 %0, %1;" : "=f"(y) : "f"(x)); return y;
}

// ---------------------------------------------------------------------------
// K_xwpre: merged xW + preT GEMMs (unchanged from R13).
// ---------------------------------------------------------------------------
__global__ __launch_bounds__(256, 2) void k_xwpre(const float* __restrict__ data,
                                                  const float* __restrict__ Wx,
                                                  const float* __restrict__ bvec,
                                                  const float* __restrict__ W1,
                                                  const float* __restrict__ b1) {
    __shared__ __align__(16) unsigned char smbuf[33280];
    int tid = threadIdx.x;

    if (blockIdx.x < 1024) {
        float* sA = (float*)smbuf;               // [2][16][132]
        float* sB = (float*)(smbuf + 16896);     // [2][16][128]
        int m0 = (blockIdx.x & 511) * 128;
        int h0 = (blockIdx.x >> 9) * 128;

        int am = tid >> 1;
        int ak = (tid & 1) * 8;
        int m = m0 + am;
        int s = m >> 9, b = m & 511;
        const float* aptr = data + (size_t)b * (TT * NN) + s * NN + ak;
        int kb = tid >> 5;
        int nb = (tid & 31) * 4;
        const float* bptr = Wx + (size_t)kb * HH + h0 + nb;

#define XA(bf, k, c) sA[((bf) * 16 + (k)) * 132 + (c)]
#define XB(bf, k, c) sB[((bf) * 16 + (k)) * 128 + (c)]

        float4 pa0 = *(const float4*)(aptr);
        float4 pa1 = *(const float4*)(aptr + 4);
        float4 pb0 = *(const float4*)(bptr);
        float4 pb1 = *(const float4*)(bptr + 8 * HH);
        {
            float av[8] = {pa0.x, pa0.y, pa0.z, pa0.w, pa1.x, pa1.y, pa1.z, pa1.w};
#pragma unroll
            for (int jj = 0; jj < 8; ++jj) XA(0, ak + jj, am) = av[jj];
            *(float4*)&XB(0, kb, nb) = pb0;
            *(float4*)&XB(0, kb + 8, nb) = pb1;
        }
        __syncthreads();

        int ty = tid >> 4, tx = tid & 15;
        int mr = ty * 8, nr = tx * 8;
        ull acc[8][4] = {};

#pragma unroll 2
        for (int c = 0; c < 8; ++c) {
            if (c + 1 < 8) {
                int k0 = (c + 1) * 16;
                pa0 = *(const float4*)(aptr + k0);
                pa1 = *(const float4*)(aptr + k0 + 4);
                pb0 = *(const float4*)(bptr + (size_t)k0 * HH);
                pb1 = *(const float4*)(bptr + (size_t)(k0 + 8) * HH);
            }
            int buf = c & 1;
#pragma unroll
            for (int k = 0; k < 16; ++k) {
                float4 a0 = *(const float4*)&XA(buf, k, mr);
                float4 a1 = *(const float4*)&XA(buf, k, mr + 4);
                F4U b0u, b1u;
                b0u.v = *(const float4*)&XB(buf, k, nr);
                b1u.v = *(const float4*)&XB(buf, k, nr + 4);
                float av[8] = {a0.x, a0.y, a0.z, a0.w, a1.x, a1.y, a1.z, a1.w};
                ull bp[4] = {b0u.u[0], b0u.u[1], b1u.u[0], b1u.u[1]};
#pragma unroll
                for (int r = 0; r < 8; ++r) {
                    ull ad = dup2(av[r]);
#pragma unroll
                    for (int p = 0; p < 4; ++p) acc[r][p] = ffma2(ad, bp[p], acc[r][p]);
                }
            }
            if (c + 1 < 8) {
                int nbuf = (c + 1) & 1;
                float av[8] = {pa0.x, pa0.y, pa0.z, pa0.w, pa1.x, pa1.y, pa1.z, pa1.w};
#pragma unroll
                for (int jj = 0; jj < 8; ++jj) XA(nbuf, ak + jj, am) = av[jj];
                *(float4*)&XB(nbuf, kb, nb) = pb0;
                *(float4*)&XB(nbuf, kb + 8, nb) = pb1;
                __syncthreads();
            }
        }

        float bias[8];
#pragma unroll
        for (int cc = 0; cc < 8; ++cc) bias[cc] = __ldg(&bvec[h0 + nr + cc]);
#pragma unroll
        for (int r = 0; r < 8; ++r) {
            float o[8];
            unpk(acc[r][0], o[0], o[1]);
            unpk(acc[r][1], o[2], o[3]);
            unpk(acc[r][2], o[4], o[5]);
            unpk(acc[r][3], o[6], o[7]);
            float* op = g_xW + (size_t)(m0 + mr + r) * HH + h0 + nr;
            float4 o0 = {o[0] + bias[0], o[1] + bias[1], o[2] + bias[2], o[3] + bias[3]};
            float4 o1 = {o[4] + bias[4], o[5] + bias[5], o[6] + bias[6], o[7] + bias[7]};
            *(float4*)&op[0] = o0;
            *(float4*)&op[4] = o1;
        }
#undef XA
#undef XB
    } else {
        float* sA = (float*)smbuf;               // [2][16][128]
        float* sB = (float*)(smbuf + 16384);     // [2][16][128]
        int b = blockIdx.x - 1024;

#define PA(bf, k, c) sA[((bf) * 16 + (k)) * 128 + (c)]
#define PB(bf, k, c) sB[((bf) * 16 + (k)) * 128 + (c)]

        int kb = tid >> 5;
        int nb = (tid & 31) * 4;
        const float* aptr = W1 + (size_t)kb * TT + nb;
        const float* bptr = data + (size_t)b * (TT * NN) + (size_t)kb * NN + nb;

        float4 pa0 = *(const float4*)(aptr);
        float4 pa1 = *(const float4*)(aptr + 8 * TT);
        float4 pb0 = *(const float4*)(bptr);
        float4 pb1 = *(const float4*)(bptr + 8 * NN);
        *(float4*)&PA(0, kb, nb) = pa0;
        *(float4*)&PA(0, kb + 8, nb) = pa1;
        *(float4*)&PB(0, kb, nb) = pb0;
        *(float4*)&PB(0, kb + 8, nb) = pb1;
        __syncthreads();

        int ty = tid >> 4, tx = tid & 15;
        int mr = ty * 8, nr = tx * 8;
        ull acc[8][4] = {};

#pragma unroll 2
        for (int c = 0; c < 8; ++c) {
            if (c + 1 < 8) {
                int k0 = (c + 1) * 16;
                pa0 = *(const float4*)(aptr + (size_t)k0 * TT);
                pa1 = *(const float4*)(aptr + (size_t)(k0 + 8) * TT);
                pb0 = *(const float4*)(bptr + (size_t)k0 * NN);
                pb1 = *(const float4*)(bptr + (size_t)(k0 + 8) * NN);
            }
            int buf = c & 1;
#pragma unroll
            for (int k = 0; k < 16; ++k) {
                float4 a0 = *(const float4*)&PA(buf, k, mr);
                float4 a1 = *(const float4*)&PA(buf, k, mr + 4);
                F4U b0u, b1u;
                b0u.v = *(const float4*)&PB(buf, k, nr);
                b1u.v = *(const float4*)&PB(buf, k, nr + 4);
                float av[8] = {a0.x, a0.y, a0.z, a0.w, a1.x, a1.y, a1.z, a1.w};
                ull bp[4] = {b0u.u[0], b0u.u[1], b1u.u[0], b1u.u[1]};
#pragma unroll
                for (int r = 0; r < 8; ++r) {
                    ull ad = dup2(av[r]);
#pragma unroll
                    for (int p = 0; p < 4; ++p) acc[r][p] = ffma2(ad, bp[p], acc[r][p]);
                }
            }
            if (c + 1 < 8) {
                int nbuf = (c + 1) & 1;
                *(float4*)&PA(nbuf, kb, nb) = pa0;
                *(float4*)&PA(nbuf, kb + 8, nb) = pa1;
                *(float4*)&PB(nbuf, kb, nb) = pb0;
                *(float4*)&PB(nbuf, kb + 8, nb) = pb1;
                __syncthreads();
            }
        }

#pragma unroll
        for (int r = 0; r < 8; ++r) {
            int t = mr + r;
            float bt = __ldg(&b1[t]);
            float o[8];
            unpk(acc[r][0], o[0], o[1]);
            unpk(acc[r][1], o[2], o[3]);
            unpk(acc[r][2], o[4], o[5]);
            unpk(acc[r][3], o[6], o[7]);
            float* op = g_preT + (size_t)b * (TT * NN) + (size_t)t * NN + nr;
            float4 o0 = {o[0] + bt, o[1] + bt, o[2] + bt, o[3] + bt};
            float4 o1 = {o[4] + bt, o[5] + bt, o[6] + bt, o[7] + bt};
            *(float4*)&op[0] = o0;
            *(float4*)&op[4] = o1;
        }
#undef PA
#undef PB
    }
}

// ---------------------------------------------------------------------------
// K_rnn9: best measured RNN (376us, profiled). Unchanged.
// ---------------------------------------------------------------------------
__global__ __launch_bounds__(512, 1) void k_rnn9(const float* __restrict__ h0,
                                                 const float* __restrict__ Wh) {
    extern __shared__ float sm[];
    float* sWs = sm;            // [128][256]
    float* sh = sm + 32768;     // [2][256][4]
    float* sred = sh + 2048;    // [256][4]
    int b0 = blockIdx.x * 4;
    int tid = threadIdx.x;
    int j = tid & 255;
    int kh = tid >> 8;

    for (int i = tid; i < 128 * 64; i += 512) {
        int row = i >> 6;
        int c4 = i & 63;
        int gr = (row < 64) ? row : (row + 64);
        ((float4*)sWs)[i] = *(const float4*)&Wh[(size_t)gr * HH + c4 * 4];
    }
    float wr[64];
    {
        const float* wp = Wh + (size_t)(kh * 128 + 64) * HH + j;
#pragma unroll
        for (int c = 0; c < 64; ++c) wr[c] = wp[(size_t)c * HH];
    }
    if (kh == 0) {
        float4 h4;
        h4.x = h0[(size_t)(b0 + 0) * HH + j];
        h4.y = h0[(size_t)(b0 + 1) * HH + j];
        h4.z = h0[(size_t)(b0 + 2) * HH + j];
        h4.w = h0[(size_t)(b0 + 3) * HH + j];
        *(float4*)&sh[j * 4] = h4;
    }
    __syncthreads();

    ull nx01 = 0, nx23 = 0;
    if (kh == 0) {
        const float* xw = g_xW + (size_t)b0 * HH + j;
        nx01 = pack2(xw[0], xw[HH]);
        nx23 = pack2(xw[2 * HH], xw[3 * HH]);
    }

    const float* swj = sWs + j;
    int smbase = kh * 64;
    int hsm = kh * 128;
    int hrg = kh * 128 + 64;

    for (int s = 0; s < TT; ++s) {
        const float* shc = sh + (s & 1) * 1024;
        float* shn = sh + (1 - (s & 1)) * 1024;

        ull a01, a23;
        if (kh == 0) {
            a01 = nx01; a23 = nx23;
            if (s + 1 < TT) {
                const float* xw = g_xW + (size_t)(s + 1) * (BB * HH) + (size_t)b0 * HH + j;
                nx01 = pack2(xw[0], xw[HH]);
                nx23 = pack2(xw[2 * HH], xw[3 * HH]);
            }
        } else {
            a01 = 0; a23 = 0;
        }
        ull c01 = 0, c23 = 0;

#pragma unroll 16
        for (int k = 0; k < 64; ++k) {
            float w = swj[(smbase + k) * 256];
            F4U hu; hu.v = *(const float4*)&shc[(hsm + k) * 4];
            ull wd = dup2(w);
            a01 = ffma2(hu.u[0], wd, a01);
            a23 = ffma2(hu.u[1], wd, a23);
        }
#pragma unroll
        for (int c = 0; c < 64; ++c) {
            ull wd = dup2(wr[c]);
            F4U hu; hu.v = *(const float4*)&shc[(hrg + c) * 4];
            c01 = ffma2(hu.u[0], wd, c01);
            c23 = ffma2(hu.u[1], wd, c23);
        }

        if (kh == 1) {
            F4U r;
            r.u[0] = fadd2(a01, c01);
            r.u[1] = fadd2(a23, c23);
            *(float4*)&sred[j * 4] = r.v;
        }
        __syncthreads();
        if (kh == 0) {
            F4U p; p.v = *(const float4*)&sred[j * 4];
            a01 = fadd2(fadd2(a01, c01), p.u[0]);
            a23 = fadd2(fadd2(a23, c23), p.u[1]);
            float x0, x1, x2, x3;
            unpk(a01, x0, x1);
            unpk(a23, x2, x3);
            float4 h4o = make_float4(tanh_fast(x0), tanh_fast(x1), tanh_fast(x2), tanh_fast(x3));
            *(float4*)&shn[j * 4] = h4o;
            *(float4*)&g_Hs2[((size_t)s * HH + j) * BB + b0] = h4o;
        }
        __syncthreads();
    }
}

// ---------------------------------------------------------------------------
// K_q3: Q[m][t] = Hs-row(m) @ W2 + b2. (unchanged)
// ---------------------------------------------------------------------------
__global__ __launch_bounds__(256, 2) void k_q3(const float* __restrict__ W2,
                                               const float* __restrict__ b2) {
    __shared__ float sA[2][16][132];
    __shared__ float sB[2][16][128];
    int m0 = blockIdx.x * 128;
    int s = m0 >> 9, b0m = m0 & 511;
    int tid = threadIdx.x;

    int kk0 = tid >> 5;
    int mmo = (tid & 31) * 4;
    int kk1 = kk0 + 8;
    const float* aB = g_Hs2 + (size_t)s * HH * BB + b0m + mmo;
    int kb = tid >> 5;
    int nb = (tid & 31) * 4;
    const float* bptr = W2 + (size_t)kb * TT + nb;

    float4 pa0 = *(const float4*)&aB[(size_t)kk0 * BB];
    float4 pa1 = *(const float4*)&aB[(size_t)kk1 * BB];
    float4 pb0 = *(const float4*)(bptr);
    float4 pb1 = *(const float4*)(bptr + 8 * TT);
    *(float4*)&sA[0][kk0][mmo] = pa0;
    *(float4*)&sA[0][kk1][mmo] = pa1;
    *(float4*)&sB[0][kb][nb] = pb0;
    *(float4*)&sB[0][kb + 8][nb] = pb1;
    __syncthreads();

    int ty = tid >> 4, tx = tid & 15;
    int mr = ty * 8, nr = tx * 8;
    ull acc[8][4] = {};

#pragma unroll 2
    for (int c = 0; c < 16; ++c) {
        if (c + 1 < 16) {
            int k0 = (c + 1) * 16;
            pa0 = *(const float4*)&aB[(size_t)(k0 + kk0) * BB];
            pa1 = *(const float4*)&aB[(size_t)(k0 + kk1) * BB];
            pb0 = *(const float4*)(bptr + (size_t)k0 * TT);
            pb1 = *(const float4*)(bptr + (size_t)(k0 + 8) * TT);
        }
        int buf = c & 1;
#pragma unroll
        for (int k = 0; k < 16; ++k) {
            float4 a0 = *(const float4*)&sA[buf][k][mr];
            float4 a1 = *(const float4*)&sA[buf][k][mr + 4];
            F4U b0u, b1u;
            b0u.v = *(const float4*)&sB[buf][k][nr];
            b1u.v = *(const float4*)&sB[buf][k][nr + 4];
            float av[8] = {a0.x, a0.y, a0.z, a0.w, a1.x, a1.y, a1.z, a1.w};
            ull bp[4] = {b0u.u[0], b0u.u[1], b1u.u[0], b1u.u[1]};
#pragma unroll
            for (int r = 0; r < 8; ++r) {
                ull ad = dup2(av[r]);
#pragma unroll
                for (int p = 0; p < 4; ++p) acc[r][p] = ffma2(ad, bp[p], acc[r][p]);
            }
        }
        if (c + 1 < 16) {
            int nbuf = (c + 1) & 1;
            *(float4*)&sA[nbuf][kk0][mmo] = pa0;
            *(float4*)&sA[nbuf][kk1][mmo] = pa1;
            *(float4*)&sB[nbuf][kb][nb] = pb0;
            *(float4*)&sB[nbuf][kb + 8][nb] = pb1;
            __syncthreads();
        }
    }

    float bias[8];
#pragma unroll
    for (int cc = 0; cc < 8; ++cc) bias[cc] = __ldg(&b2[nr + cc]);
#pragma unroll
    for (int r = 0; r < 8; ++r) {
        float o[8];
        unpk(acc[r][0], o[0], o[1]);
        unpk(acc[r][1], o[2], o[3]);
        unpk(acc[r][2], o[4], o[5]);
        unpk(acc[r][3], o[6], o[7]);
        float* op = g_Q + (size_t)(m0 + mr + r) * TT + nr;
        float4 o0 = {o[0] + bias[0], o[1] + bias[1], o[2] + bias[2], o[3] + bias[3]};
        float4 o1 = {o[4] + bias[4], o[5] + bias[5], o[6] + bias[6], o[7] + bias[7]};
        *(float4*)&op[0] = o0;
        *(float4*)&op[4] = o1;
    }
}

// ---------------------------------------------------------------------------
// K_att7: att6 with TRANSPOSED pre tile sPT[n][t] (pad 132) and float4
// vectorized t-loop: per 4 t -> 1 LDS.128 (conflict-free) + 2 float4
// broadcasts = 6 crossbar cyc vs 12 (attacks the measured L1=79.5% wall).
// Single barrier/iter, double-buffered sQ/sred, q-prefetch.
// ---------------------------------------------------------------------------
__global__ __launch_bounds__(256) void k_att7(const float* __restrict__ data,
                                              const float* __restrict__ Wv,
                                              float* __restrict__ out) {
    extern __shared__ float sm[];
    float* sPT = sm;            // [128][132]  sPT[n][t]
    float* sQ = sm + 16896;     // [2][256]
    float* sWv = sQ + 512;      // [128]
    float* sred = sWv + 128;    // [2][8]
    int b = blockIdx.x >> 2;
    int sq = blockIdx.x & 3;
    int tid = threadIdx.x;

    // transposed fill: gP is [t][n]; write sPT[n][t]
    const float4* gP = (const float4*)(g_preT + (size_t)b * (TT * NN));
    for (int i = tid; i < 4096; i += 256) {
        int t = i >> 5;
        int n4 = (i & 31) * 4;
        float4 v = gP[i];
        sPT[(n4 + 0) * 132 + t] = v.x;
        sPT[(n4 + 1) * 132 + t] = v.y;
        sPT[(n4 + 2) * 132 + t] = v.z;
        sPT[(n4 + 3) * 132 + t] = v.w;
    }
    if (tid < 128) sWv[tid] = Wv[tid];

    int n = tid & 127;
    int grp = tid >> 7;
    int lane = tid & 31;
    int wig = (tid >> 5) & 3;

    sQ[tid] = g_Q[(size_t)(sq * 32 + grp) * (BB * TT) + b * TT + n];
    __syncthreads();

    const float* prow = sPT + n * 132;

    for (int si = 0; si < 16; ++si) {
        int cur = si & 1;
        int s = sq * 32 + si * 2 + grp;

        float qn = 0.f;
        if (si + 1 < 16) {
            qn = g_Q[(size_t)(s + 2) * (BB * TT) + b * TT + n];
        }

        const float* qrow = sQ + cur * 256 + grp * 128;
        float e0 = 0.f, e1 = 0.f;
#pragma unroll 8
        for (int t4 = 0; t4 < 32; ++t4) {
            float4 pv = *(const float4*)&prow[t4 * 4];
            float4 qv = *(const float4*)&qrow[t4 * 4];
            float4 wv = *(const float4*)&sWv[t4 * 4];
            e0 += wv.x * tanh_fast(pv.x + qv.x);
            e1 += wv.y * tanh_fast(pv.y + qv.y);
            e0 += wv.z * tanh_fast(pv.z + qv.z);
            e1 += wv.w * tanh_fast(pv.w + qv.w);
        }
        float e = e0 + e1;

        float ex = __expf(e);
        float sum = ex;
#pragma unroll
        for (int o = 16; o; o >>= 1) sum += __shfl_xor_sync(0xFFFFFFFFu, sum, o);
        if (lane == 0) sred[cur * 8 + grp * 4 + wig] = sum;
        if (si + 1 < 16) sQ[(cur ^ 1) * 256 + tid] = qn;
        __syncthreads();

        const float* sr = sred + cur * 8 + grp * 4;
        sum = sr[0] + sr[1] + sr[2] + sr[3];
        float alpha = ex / sum;

        int bp = 4 * s + (b >> 7);
        int tp = b & 127;
        size_t idx = (size_t)bp * (TT * NN) + tp * NN + n;
        out[idx] = data[idx] * alpha;
    }
}

// ---------------------------------------------------------------------------
extern "C" void kernel_launch(void* const* d_in, const int* in_sizes, int n_in,
                              void* d_out, int out_size) {
    const float* data = (const float*)d_in[0];
    const float* h0 = (const float*)d_in[1];
    const float* Wx = (const float*)d_in[2];
    const float* Wh = (const float*)d_in[3];
    const float* bvec = (const float*)d_in[4];
    const float* W1 = (const float*)d_in[5];
    const float* b1 = (const float*)d_in[6];
    const float* W2 = (const float*)d_in[7];
    const float* b2 = (const float*)d_in[8];
    const float* Wv = (const float*)d_in[9];
    float* out = (float*)d_out;

    const int SM_RNN = (32768 + 2048 + 1024) * 4;      // 140 KB
    const int SM_ATT = (16896 + 512 + 128 + 16) * 4;   // 70,208 B

    cudaFuncSetAttribute(k_rnn9, cudaFuncAttributeMaxDynamicSharedMemorySize, SM_RNN);
    cudaFuncSetAttribute(k_att7, cudaFuncAttributeMaxDynamicSharedMemorySize, SM_ATT);

    k_xwpre<<<1536, 256>>>(data, Wx, bvec, W1, b1);
    k_rnn9<<<BB / 4, 512, SM_RNN>>>(h0, Wh);
    k_q3<<<(TT * BB) / 128, 256>>>(W2, b2);
    k_att7<<<BB * 4, 256, SM_ATT>>>(data, Wv, out);
}

// round 15
// speedup vs baseline: 1.0384x; 1.0384x over previous
#include <cuda_runtime.h>

// Shapes: B=512, T=128, N=128, H=256
#define BB 512
#define TT 128
#define NN 128
#define HH 256

__device__ float g_xW[TT * BB * HH];   // [s][b][h]
__device__ float g_Hs2[TT * HH * BB];  // [s][h][b]
__device__ float g_Q[TT * BB * TT];    // [s][b][t]
__device__ float g_preT[BB * TT * NN]; // [b][t][n]

typedef unsigned long long ull;

__device__ __forceinline__ ull pack2(float x, float y) {
    ull r; asm("mov.b64 %0, {%1, %2};" : "=l"(r) : "f"(x), "f"(y)); return r;
}
__device__ __forceinline__ ull dup2(float x) {
    ull r; asm("mov.b64 %0, {%1, %1};" : "=l"(r) : "f"(x)); return r;
}
__device__ __forceinline__ ull ffma2(ull a, ull b, ull c) {
    ull d; asm("fma.rn.f32x2 %0, %1, %2, %3;" : "=l"(d) : "l"(a), "l"(b), "l"(c)); return d;
}
__device__ __forceinline__ ull fadd2(ull a, ull b) {
    ull d; asm("add.rn.f32x2 %0, %1, %2;" : "=l"(d) : "l"(a), "l"(b)); return d;
}
__device__ __forceinline__ void unpk(ull p, float& x, float& y) {
    asm("mov.b64 {%0, %1}, %2;" : "=f"(x), "=f"(y) : "l"(p));
}
union F4U { float4 v; ull u[2]; };

__device__ __forceinline__ float tanh_fast(float x) {
    float y; asm("tanh.approx.f32 %0, %1;" : "=f"(y) : "f"(x)); return y;
}

// ---------------------------------------------------------------------------
// K_xwpre: merged xW + preT GEMMs (unchanged from R13).
// ---------------------------------------------------------------------------
__global__ __launch_bounds__(256, 2) void k_xwpre(const float* __restrict__ data,
                                                  const float* __restrict__ Wx,
                                                  const float* __restrict__ bvec,
                                                  const float* __restrict__ W1,
                                                  const float* __restrict__ b1) {
    __shared__ __align__(16) unsigned char smbuf[33280];
    int tid = threadIdx.x;

    if (blockIdx.x < 1024) {
        float* sA = (float*)smbuf;               // [2][16][132]
        float* sB = (float*)(smbuf + 16896);     // [2][16][128]
        int m0 = (blockIdx.x & 511) * 128;
        int h0 = (blockIdx.x >> 9) * 128;

        int am = tid >> 1;
        int ak = (tid & 1) * 8;
        int m = m0 + am;
        int s = m >> 9, b = m & 511;
        const float* aptr = data + (size_t)b * (TT * NN) + s * NN + ak;
        int kb = tid >> 5;
        int nb = (tid & 31) * 4;
        const float* bptr = Wx + (size_t)kb * HH + h0 + nb;

#define XA(bf, k, c) sA[((bf) * 16 + (k)) * 132 + (c)]
#define XB(bf, k, c) sB[((bf) * 16 + (k)) * 128 + (c)]

        float4 pa0 = *(const float4*)(aptr);
        float4 pa1 = *(const float4*)(aptr + 4);
        float4 pb0 = *(const float4*)(bptr);
        float4 pb1 = *(const float4*)(bptr + 8 * HH);
        {
            float av[8] = {pa0.x, pa0.y, pa0.z, pa0.w, pa1.x, pa1.y, pa1.z, pa1.w};
#pragma unroll
            for (int jj = 0; jj < 8; ++jj) XA(0, ak + jj, am) = av[jj];
            *(float4*)&XB(0, kb, nb) = pb0;
            *(float4*)&XB(0, kb + 8, nb) = pb1;
        }
        __syncthreads();

        int ty = tid >> 4, tx = tid & 15;
        int mr = ty * 8, nr = tx * 8;
        ull acc[8][4] = {};

#pragma unroll 2
        for (int c = 0; c < 8; ++c) {
            if (c + 1 < 8) {
                int k0 = (c + 1) * 16;
                pa0 = *(const float4*)(aptr + k0);
                pa1 = *(const float4*)(aptr + k0 + 4);
                pb0 = *(const float4*)(bptr + (size_t)k0 * HH);
                pb1 = *(const float4*)(bptr + (size_t)(k0 + 8) * HH);
            }
            int buf = c & 1;
#pragma unroll
            for (int k = 0; k < 16; ++k) {
                float4 a0 = *(const float4*)&XA(buf, k, mr);
                float4 a1 = *(const float4*)&XA(buf, k, mr + 4);
                F4U b0u, b1u;
                b0u.v = *(const float4*)&XB(buf, k, nr);
                b1u.v = *(const float4*)&XB(buf, k, nr + 4);
                float av[8] = {a0.x, a0.y, a0.z, a0.w, a1.x, a1.y, a1.z, a1.w};
                ull bp[4] = {b0u.u[0], b0u.u[1], b1u.u[0], b1u.u[1]};
#pragma unroll
                for (int r = 0; r < 8; ++r) {
                    ull ad = dup2(av[r]);
#pragma unroll
                    for (int p = 0; p < 4; ++p) acc[r][p] = ffma2(ad, bp[p], acc[r][p]);
                }
            }
            if (c + 1 < 8) {
                int nbuf = (c + 1) & 1;
                float av[8] = {pa0.x, pa0.y, pa0.z, pa0.w, pa1.x, pa1.y, pa1.z, pa1.w};
#pragma unroll
                for (int jj = 0; jj < 8; ++jj) XA(nbuf, ak + jj, am) = av[jj];
                *(float4*)&XB(nbuf, kb, nb) = pb0;
                *(float4*)&XB(nbuf, kb + 8, nb) = pb1;
                __syncthreads();
            }
        }

        float bias[8];
#pragma unroll
        for (int cc = 0; cc < 8; ++cc) bias[cc] = __ldg(&bvec[h0 + nr + cc]);
#pragma unroll
        for (int r = 0; r < 8; ++r) {
            float o[8];
            unpk(acc[r][0], o[0], o[1]);
            unpk(acc[r][1], o[2], o[3]);
            unpk(acc[r][2], o[4], o[5]);
            unpk(acc[r][3], o[6], o[7]);
            float* op = g_xW + (size_t)(m0 + mr + r) * HH + h0 + nr;
            float4 o0 = {o[0] + bias[0], o[1] + bias[1], o[2] + bias[2], o[3] + bias[3]};
            float4 o1 = {o[4] + bias[4], o[5] + bias[5], o[6] + bias[6], o[7] + bias[7]};
            *(float4*)&op[0] = o0;
            *(float4*)&op[4] = o1;
        }
#undef XA
#undef XB
    } else {
        float* sA = (float*)smbuf;               // [2][16][128]
        float* sB = (float*)(smbuf + 16384);     // [2][16][128]
        int b = blockIdx.x - 1024;

#define PA(bf, k, c) sA[((bf) * 16 + (k)) * 128 + (c)]
#define PB(bf, k, c) sB[((bf) * 16 + (k)) * 128 + (c)]

        int kb = tid >> 5;
        int nb = (tid & 31) * 4;
        const float* aptr = W1 + (size_t)kb * TT + nb;
        const float* bptr = data + (size_t)b * (TT * NN) + (size_t)kb * NN + nb;

        float4 pa0 = *(const float4*)(aptr);
        float4 pa1 = *(const float4*)(aptr + 8 * TT);
        float4 pb0 = *(const float4*)(bptr);
        float4 pb1 = *(const float4*)(bptr + 8 * NN);
        *(float4*)&PA(0, kb, nb) = pa0;
        *(float4*)&PA(0, kb + 8, nb) = pa1;
        *(float4*)&PB(0, kb, nb) = pb0;
        *(float4*)&PB(0, kb + 8, nb) = pb1;
        __syncthreads();

        int ty = tid >> 4, tx = tid & 15;
        int mr = ty * 8, nr = tx * 8;
        ull acc[8][4] = {};

#pragma unroll 2
        for (int c = 0; c < 8; ++c) {
            if (c + 1 < 8) {
                int k0 = (c + 1) * 16;
                pa0 = *(const float4*)(aptr + (size_t)k0 * TT);
                pa1 = *(const float4*)(aptr + (size_t)(k0 + 8) * TT);
                pb0 = *(const float4*)(bptr + (size_t)k0 * NN);
                pb1 = *(const float4*)(bptr + (size_t)(k0 + 8) * NN);
            }
            int buf = c & 1;
#pragma unroll
            for (int k = 0; k < 16; ++k) {
                float4 a0 = *(const float4*)&PA(buf, k, mr);
                float4 a1 = *(const float4*)&PA(buf, k, mr + 4);
                F4U b0u, b1u;
                b0u.v = *(const float4*)&PB(buf, k, nr);
                b1u.v = *(const float4*)&PB(buf, k, nr + 4);
                float av[8] = {a0.x, a0.y, a0.z, a0.w, a1.x, a1.y, a1.z, a1.w};
                ull bp[4] = {b0u.u[0], b0u.u[1], b1u.u[0], b1u.u[1]};
#pragma unroll
                for (int r = 0; r < 8; ++r) {
                    ull ad = dup2(av[r]);
#pragma unroll
                    for (int p = 0; p < 4; ++p) acc[r][p] = ffma2(ad, bp[p], acc[r][p]);
                }
            }
            if (c + 1 < 8) {
                int nbuf = (c + 1) & 1;
                *(float4*)&PA(nbuf, kb, nb) = pa0;
                *(float4*)&PA(nbuf, kb + 8, nb) = pa1;
                *(float4*)&PB(nbuf, kb, nb) = pb0;
                *(float4*)&PB(nbuf, kb + 8, nb) = pb1;
                __syncthreads();
            }
        }

#pragma unroll
        for (int r = 0; r < 8; ++r) {
            int t = mr + r;
            float bt = __ldg(&b1[t]);
            float o[8];
            unpk(acc[r][0], o[0], o[1]);
            unpk(acc[r][1], o[2], o[3]);
            unpk(acc[r][2], o[4], o[5]);
            unpk(acc[r][3], o[6], o[7]);
            float* op = g_preT + (size_t)b * (TT * NN) + (size_t)t * NN + nr;
            float4 o0 = {o[0] + bt, o[1] + bt, o[2] + bt, o[3] + bt};
            float4 o1 = {o[4] + bt, o[5] + bt, o[6] + bt, o[7] + bt};
            *(float4*)&op[0] = o0;
            *(float4*)&op[4] = o1;
        }
#undef PA
#undef PB
    }
}

// ---------------------------------------------------------------------------
// K_rnn9: best measured RNN (376us, profiled). Unchanged.
// ---------------------------------------------------------------------------
__global__ __launch_bounds__(512, 1) void k_rnn9(const float* __restrict__ h0,
                                                 const float* __restrict__ Wh) {
    extern __shared__ float sm[];
    float* sWs = sm;            // [128][256]
    float* sh = sm + 32768;     // [2][256][4]
    float* sred = sh + 2048;    // [256][4]
    int b0 = blockIdx.x * 4;
    int tid = threadIdx.x;
    int j = tid & 255;
    int kh = tid >> 8;

    for (int i = tid; i < 128 * 64; i += 512) {
        int row = i >> 6;
        int c4 = i & 63;
        int gr = (row < 64) ? row : (row + 64);
        ((float4*)sWs)[i] = *(const float4*)&Wh[(size_t)gr * HH + c4 * 4];
    }
    float wr[64];
    {
        const float* wp = Wh + (size_t)(kh * 128 + 64) * HH + j;
#pragma unroll
        for (int c = 0; c < 64; ++c) wr[c] = wp[(size_t)c * HH];
    }
    if (kh == 0) {
        float4 h4;
        h4.x = h0[(size_t)(b0 + 0) * HH + j];
        h4.y = h0[(size_t)(b0 + 1) * HH + j];
        h4.z = h0[(size_t)(b0 + 2) * HH + j];
        h4.w = h0[(size_t)(b0 + 3) * HH + j];
        *(float4*)&sh[j * 4] = h4;
    }
    __syncthreads();

    ull nx01 = 0, nx23 = 0;
    if (kh == 0) {
        const float* xw = g_xW + (size_t)b0 * HH + j;
        nx01 = pack2(xw[0], xw[HH]);
        nx23 = pack2(xw[2 * HH], xw[3 * HH]);
    }

    const float* swj = sWs + j;
    int smbase = kh * 64;
    int hsm = kh * 128;
    int hrg = kh * 128 + 64;

    for (int s = 0; s < TT; ++s) {
        const float* shc = sh + (s & 1) * 1024;
        float* shn = sh + (1 - (s & 1)) * 1024;

        ull a01, a23;
        if (kh == 0) {
            a01 = nx01; a23 = nx23;
            if (s + 1 < TT) {
                const float* xw = g_xW + (size_t)(s + 1) * (BB * HH) + (size_t)b0 * HH + j;
                nx01 = pack2(xw[0], xw[HH]);
                nx23 = pack2(xw[2 * HH], xw[3 * HH]);
            }
        } else {
            a01 = 0; a23 = 0;
        }
        ull c01 = 0, c23 = 0;

#pragma unroll 16
        for (int k = 0; k < 64; ++k) {
            float w = swj[(smbase + k) * 256];
            F4U hu; hu.v = *(const float4*)&shc[(hsm + k) * 4];
            ull wd = dup2(w);
            a01 = ffma2(hu.u[0], wd, a01);
            a23 = ffma2(hu.u[1], wd, a23);
        }
#pragma unroll
        for (int c = 0; c < 64; ++c) {
            ull wd = dup2(wr[c]);
            F4U hu; hu.v = *(const float4*)&shc[(hrg + c) * 4];
            c01 = ffma2(hu.u[0], wd, c01);
            c23 = ffma2(hu.u[1], wd, c23);
        }

        if (kh == 1) {
            F4U r;
            r.u[0] = fadd2(a01, c01);
            r.u[1] = fadd2(a23, c23);
            *(float4*)&sred[j * 4] = r.v;
        }
        __syncthreads();
        if (kh == 0) {
            F4U p; p.v = *(const float4*)&sred[j * 4];
            a01 = fadd2(fadd2(a01, c01), p.u[0]);
            a23 = fadd2(fadd2(a23, c23), p.u[1]);
            float x0, x1, x2, x3;
            unpk(a01, x0, x1);
            unpk(a23, x2, x3);
            float4 h4o = make_float4(tanh_fast(x0), tanh_fast(x1), tanh_fast(x2), tanh_fast(x3));
            *(float4*)&shn[j * 4] = h4o;
            *(float4*)&g_Hs2[((size_t)s * HH + j) * BB + b0] = h4o;
        }
        __syncthreads();
    }
}

// ---------------------------------------------------------------------------
// K_q3: Q[m][t] = Hs-row(m) @ W2 + b2. (unchanged)
// ---------------------------------------------------------------------------
__global__ __launch_bounds__(256, 2) void k_q3(const float* __restrict__ W2,
                                               const float* __restrict__ b2) {
    __shared__ float sA[2][16][132];
    __shared__ float sB[2][16][128];
    int m0 = blockIdx.x * 128;
    int s = m0 >> 9, b0m = m0 & 511;
    int tid = threadIdx.x;

    int kk0 = tid >> 5;
    int mmo = (tid & 31) * 4;
    int kk1 = kk0 + 8;
    const float* aB = g_Hs2 + (size_t)s * HH * BB + b0m + mmo;
    int kb = tid >> 5;
    int nb = (tid & 31) * 4;
    const float* bptr = W2 + (size_t)kb * TT + nb;

    float4 pa0 = *(const float4*)&aB[(size_t)kk0 * BB];
    float4 pa1 = *(const float4*)&aB[(size_t)kk1 * BB];
    float4 pb0 = *(const float4*)(bptr);
    float4 pb1 = *(const float4*)(bptr + 8 * TT);
    *(float4*)&sA[0][kk0][mmo] = pa0;
    *(float4*)&sA[0][kk1][mmo] = pa1;
    *(float4*)&sB[0][kb][nb] = pb0;
    *(float4*)&sB[0][kb + 8][nb] = pb1;
    __syncthreads();

    int ty = tid >> 4, tx = tid & 15;
    int mr = ty * 8, nr = tx * 8;
    ull acc[8][4] = {};

#pragma unroll 2
    for (int c = 0; c < 16; ++c) {
        if (c + 1 < 16) {
            int k0 = (c + 1) * 16;
            pa0 = *(const float4*)&aB[(size_t)(k0 + kk0) * BB];
            pa1 = *(const float4*)&aB[(size_t)(k0 + kk1) * BB];
            pb0 = *(const float4*)(bptr + (size_t)k0 * TT);
            pb1 = *(const float4*)(bptr + (size_t)(k0 + 8) * TT);
        }
        int buf = c & 1;
#pragma unroll
        for (int k = 0; k < 16; ++k) {
            float4 a0 = *(const float4*)&sA[buf][k][mr];
            float4 a1 = *(const float4*)&sA[buf][k][mr + 4];
            F4U b0u, b1u;
            b0u.v = *(const float4*)&sB[buf][k][nr];
            b1u.v = *(const float4*)&sB[buf][k][nr + 4];
            float av[8] = {a0.x, a0.y, a0.z, a0.w, a1.x, a1.y, a1.z, a1.w};
            ull bp[4] = {b0u.u[0], b0u.u[1], b1u.u[0], b1u.u[1]};
#pragma unroll
            for (int r = 0; r < 8; ++r) {
                ull ad = dup2(av[r]);
#pragma unroll
                for (int p = 0; p < 4; ++p) acc[r][p] = ffma2(ad, bp[p], acc[r][p]);
            }
        }
        if (c + 1 < 16) {
            int nbuf = (c + 1) & 1;
            *(float4*)&sA[nbuf][kk0][mmo] = pa0;
            *(float4*)&sA[nbuf][kk1][mmo] = pa1;
            *(float4*)&sB[nbuf][kb][nb] = pb0;
            *(float4*)&sB[nbuf][kb + 8][nb] = pb1;
            __syncthreads();
        }
    }

    float bias[8];
#pragma unroll
    for (int cc = 0; cc < 8; ++cc) bias[cc] = __ldg(&b2[nr + cc]);
#pragma unroll
    for (int r = 0; r < 8; ++r) {
        float o[8];
        unpk(acc[r][0], o[0], o[1]);
        unpk(acc[r][1], o[2], o[3]);
        unpk(acc[r][2], o[4], o[5]);
        unpk(acc[r][3], o[6], o[7]);
        float* op = g_Q + (size_t)(m0 + mr + r) * TT + nr;
        float4 o0 = {o[0] + bias[0], o[1] + bias[1], o[2] + bias[2], o[3] + bias[3]};
        float4 o1 = {o[4] + bias[4], o[5] + bias[5], o[6] + bias[6], o[7] + bias[7]};
        *(float4*)&op[0] = o0;
        *(float4*)&op[4] = o1;
    }
}

// ---------------------------------------------------------------------------
// K_att8: att6 (sP[t][n] layout — scalar loads are perfectly conflict-free)
// with the Wv and q broadcasts VECTORIZED to float4: per 4 t the LSU work
// drops from 12 LDS to 6 (4 scalar sP + 2 broadcast LDS.128), pushing the
// kernel from crossbar-bound toward the MUFU floor. att7's transpose
// reverted (it was 8-way bank-conflicted: (4n+t) mod 32 collides at n+8).
// ---------------------------------------------------------------------------
__global__ __launch_bounds__(256) void k_att8(const float* __restrict__ data,
                                              const float* __restrict__ Wv,
                                              float* __restrict__ out) {
    extern __shared__ float sm[];
    float* sP = sm;            // [128][128]  sP[t][n]
    float* sQ = sm + 16384;    // [2][256]
    float* sWv = sQ + 512;     // [128]
    float* sred = sWv + 128;   // [2][8]
    int b = blockIdx.x >> 2;
    int sq = blockIdx.x & 3;
    int tid = threadIdx.x;

    const float4* gP = (const float4*)(g_preT + (size_t)b * (TT * NN));
    for (int i = tid; i < 4096; i += 256) ((float4*)sP)[i] = gP[i];
    if (tid < 128) sWv[tid] = Wv[tid];

    int n = tid & 127;
    int grp = tid >> 7;
    int lane = tid & 31;
    int wig = (tid >> 5) & 3;

    sQ[tid] = g_Q[(size_t)(sq * 32 + grp) * (BB * TT) + b * TT + n];
    __syncthreads();

    const float4* wv4 = (const float4*)sWv;

    for (int si = 0; si < 16; ++si) {
        int cur = si & 1;
        int s = sq * 32 + si * 2 + grp;

        float qn = 0.f;
        if (si + 1 < 16) {
            qn = g_Q[(size_t)(s + 2) * (BB * TT) + b * TT + n];
        }

        const float4* qrow4 = (const float4*)(sQ + cur * 256 + grp * 128);
        float e0 = 0.f, e1 = 0.f;
#pragma unroll 8
        for (int t4 = 0; t4 < 32; ++t4) {
            float4 qv = qrow4[t4];      // broadcast LDS.128
            float4 wv = wv4[t4];        // broadcast LDS.128
            int t = t4 * 4;
            e0 += wv.x * tanh_fast(sP[(t + 0) * 128 + n] + qv.x);
            e1 += wv.y * tanh_fast(sP[(t + 1) * 128 + n] + qv.y);
            e0 += wv.z * tanh_fast(sP[(t + 2) * 128 + n] + qv.z);
            e1 += wv.w * tanh_fast(sP[(t + 3) * 128 + n] + qv.w);
        }
        float e = e0 + e1;

        float ex = __expf(e);
        float sum = ex;
#pragma unroll
        for (int o = 16; o; o >>= 1) sum += __shfl_xor_sync(0xFFFFFFFFu, sum, o);
        if (lane == 0) sred[cur * 8 + grp * 4 + wig] = sum;
        if (si + 1 < 16) sQ[(cur ^ 1) * 256 + tid] = qn;
        __syncthreads();

        const float* sr = sred + cur * 8 + grp * 4;
        sum = sr[0] + sr[1] + sr[2] + sr[3];
        float alpha = ex / sum;

        int bp = 4 * s + (b >> 7);
        int tp = b & 127;
        size_t idx = (size_t)bp * (TT * NN) + tp * NN + n;
        out[idx] = data[idx] * alpha;
    }
}

// ---------------------------------------------------------------------------
extern "C" void kernel_launch(void* const* d_in, const int* in_sizes, int n_in,
                              void* d_out, int out_size) {
    const float* data = (const float*)d_in[0];
    const float* h0 = (const float*)d_in[1];
    const float* Wx = (const float*)d_in[2];
    const float* Wh = (const float*)d_in[3];
    const float* bvec = (const float*)d_in[4];
    const float* W1 = (const float*)d_in[5];
    const float* b1 = (const float*)d_in[6];
    const float* W2 = (const float*)d_in[7];
    const float* b2 = (const float*)d_in[8];
    const float* Wv = (const float*)d_in[9];
    float* out = (float*)d_out;

    const int SM_RNN = (32768 + 2048 + 1024) * 4;    // 140 KB
    const int SM_ATT = (16384 + 512 + 128 + 16) * 4; // ~68 KB

    cudaFuncSetAttribute(k_rnn9, cudaFuncAttributeMaxDynamicSharedMemorySize, SM_RNN);
    cudaFuncSetAttribute(k_att8, cudaFuncAttributeMaxDynamicSharedMemorySize, SM_ATT);

    k_xwpre<<<1536, 256>>>(data, Wx, bvec, W1, b1);
    k_rnn9<<<BB / 4, 512, SM_RNN>>>(h0, Wh);
    k_q3<<<(TT * BB) / 128, 256>>>(W2, b2);
    k_att8<<<BB * 4, 256, SM_ATT>>>(data, Wv, out);
}

// round 16
// speedup vs baseline: 1.0771x; 1.0372x over previous
#include <cuda_runtime.h>

// Shapes: B=512, T=128, N=128, H=256
#define BB 512
#define TT 128
#define NN 128
#define HH 256

__device__ float g_xW[TT * BB * HH];   // [s][b][h]
__device__ float g_Hs2[TT * HH * BB];  // [s][h][b]
__device__ float g_Q[TT * BB * TT];    // [s][b][t]
__device__ float g_preT[BB * TT * NN]; // [b][t][n]

typedef unsigned long long ull;

__device__ __forceinline__ ull pack2(float x, float y) {
    ull r; asm("mov.b64 %0, {%1, %2};" : "=l"(r) : "f"(x), "f"(y)); return r;
}
__device__ __forceinline__ ull dup2(float x) {
    ull r; asm("mov.b64 %0, {%1, %1};" : "=l"(r) : "f"(x)); return r;
}
__device__ __forceinline__ ull ffma2(ull a, ull b, ull c) {
    ull d; asm("fma.rn.f32x2 %0, %1, %2, %3;" : "=l"(d) : "l"(a), "l"(b), "l"(c)); return d;
}
__device__ __forceinline__ ull fadd2(ull a, ull b) {
    ull d; asm("add.rn.f32x2 %0, %1, %2;" : "=l"(d) : "l"(a), "l"(b)); return d;
}
__device__ __forceinline__ void unpk(ull p, float& x, float& y) {
    asm("mov.b64 {%0, %1}, %2;" : "=f"(x), "=f"(y) : "l"(p));
}
union F4U { float4 v; ull u[2]; };

__device__ __forceinline__ float tanh_fast(float x) {
    float y; asm("tanh.approx.f32 %0, %1;" : "=f"(y) : "f"(x)); return y;
}

// ---------------------------------------------------------------------------
// K_xwpre: merged xW + preT GEMMs (unchanged).
// ---------------------------------------------------------------------------
__global__ __launch_bounds__(256, 2) void k_xwpre(const float* __restrict__ data,
                                                  const float* __restrict__ Wx,
                                                  const float* __restrict__ bvec,
                                                  const float* __restrict__ W1,
                                                  const float* __restrict__ b1) {
    __shared__ __align__(16) unsigned char smbuf[33280];
    int tid = threadIdx.x;

    if (blockIdx.x < 1024) {
        float* sA = (float*)smbuf;               // [2][16][132]
        float* sB = (float*)(smbuf + 16896);     // [2][16][128]
        int m0 = (blockIdx.x & 511) * 128;
        int h0 = (blockIdx.x >> 9) * 128;

        int am = tid >> 1;
        int ak = (tid & 1) * 8;
        int m = m0 + am;
        int s = m >> 9, b = m & 511;
        const float* aptr = data + (size_t)b * (TT * NN) + s * NN + ak;
        int kb = tid >> 5;
        int nb = (tid & 31) * 4;
        const float* bptr = Wx + (size_t)kb * HH + h0 + nb;

#define XA(bf, k, c) sA[((bf) * 16 + (k)) * 132 + (c)]
#define XB(bf, k, c) sB[((bf) * 16 + (k)) * 128 + (c)]

        float4 pa0 = *(const float4*)(aptr);
        float4 pa1 = *(const float4*)(aptr + 4);
        float4 pb0 = *(const float4*)(bptr);
        float4 pb1 = *(const float4*)(bptr + 8 * HH);
        {
            float av[8] = {pa0.x, pa0.y, pa0.z, pa0.w, pa1.x, pa1.y, pa1.z, pa1.w};
#pragma unroll
            for (int jj = 0; jj < 8; ++jj) XA(0, ak + jj, am) = av[jj];
            *(float4*)&XB(0, kb, nb) = pb0;
            *(float4*)&XB(0, kb + 8, nb) = pb1;
        }
        __syncthreads();

        int ty = tid >> 4, tx = tid & 15;
        int mr = ty * 8, nr = tx * 8;
        ull acc[8][4] = {};

#pragma unroll 2
        for (int c = 0; c < 8; ++c) {
            if (c + 1 < 8) {
                int k0 = (c + 1) * 16;
                pa0 = *(const float4*)(aptr + k0);
                pa1 = *(const float4*)(aptr + k0 + 4);
                pb0 = *(const float4*)(bptr + (size_t)k0 * HH);
                pb1 = *(const float4*)(bptr + (size_t)(k0 + 8) * HH);
            }
            int buf = c & 1;
#pragma unroll
            for (int k = 0; k < 16; ++k) {
                float4 a0 = *(const float4*)&XA(buf, k, mr);
                float4 a1 = *(const float4*)&XA(buf, k, mr + 4);
                F4U b0u, b1u;
                b0u.v = *(const float4*)&XB(buf, k, nr);
                b1u.v = *(const float4*)&XB(buf, k, nr + 4);
                float av[8] = {a0.x, a0.y, a0.z, a0.w, a1.x, a1.y, a1.z, a1.w};
                ull bp[4] = {b0u.u[0], b0u.u[1], b1u.u[0], b1u.u[1]};
#pragma unroll
                for (int r = 0; r < 8; ++r) {
                    ull ad = dup2(av[r]);
#pragma unroll
                    for (int p = 0; p < 4; ++p) acc[r][p] = ffma2(ad, bp[p], acc[r][p]);
                }
            }
            if (c + 1 < 8) {
                int nbuf = (c + 1) & 1;
                float av[8] = {pa0.x, pa0.y, pa0.z, pa0.w, pa1.x, pa1.y, pa1.z, pa1.w};
#pragma unroll
                for (int jj = 0; jj < 8; ++jj) XA(nbuf, ak + jj, am) = av[jj];
                *(float4*)&XB(nbuf, kb, nb) = pb0;
                *(float4*)&XB(nbuf, kb + 8, nb) = pb1;
                __syncthreads();
            }
        }

        float bias[8];
#pragma unroll
        for (int cc = 0; cc < 8; ++cc) bias[cc] = __ldg(&bvec[h0 + nr + cc]);
#pragma unroll
        for (int r = 0; r < 8; ++r) {
            float o[8];
            unpk(acc[r][0], o[0], o[1]);
            unpk(acc[r][1], o[2], o[3]);
            unpk(acc[r][2], o[4], o[5]);
            unpk(acc[r][3], o[6], o[7]);
            float* op = g_xW + (size_t)(m0 + mr + r) * HH + h0 + nr;
            float4 o0 = {o[0] + bias[0], o[1] + bias[1], o[2] + bias[2], o[3] + bias[3]};
            float4 o1 = {o[4] + bias[4], o[5] + bias[5], o[6] + bias[6], o[7] + bias[7]};
            *(float4*)&op[0] = o0;
            *(float4*)&op[4] = o1;
        }
#undef XA
#undef XB
    } else {
        float* sA = (float*)smbuf;               // [2][16][128]
        float* sB = (float*)(smbuf + 16384);     // [2][16][128]
        int b = blockIdx.x - 1024;

#define PA(bf, k, c) sA[((bf) * 16 + (k)) * 128 + (c)]
#define PB(bf, k, c) sB[((bf) * 16 + (k)) * 128 + (c)]

        int kb = tid >> 5;
        int nb = (tid & 31) * 4;
        const float* aptr = W1 + (size_t)kb * TT + nb;
        const float* bptr = data + (size_t)b * (TT * NN) + (size_t)kb * NN + nb;

        float4 pa0 = *(const float4*)(aptr);
        float4 pa1 = *(const float4*)(aptr + 8 * TT);
        float4 pb0 = *(const float4*)(bptr);
        float4 pb1 = *(const float4*)(bptr + 8 * NN);
        *(float4*)&PA(0, kb, nb) = pa0;
        *(float4*)&PA(0, kb + 8, nb) = pa1;
        *(float4*)&PB(0, kb, nb) = pb0;
        *(float4*)&PB(0, kb + 8, nb) = pb1;
        __syncthreads();

        int ty = tid >> 4, tx = tid & 15;
        int mr = ty * 8, nr = tx * 8;
        ull acc[8][4] = {};

#pragma unroll 2
        for (int c = 0; c < 8; ++c) {
            if (c + 1 < 8) {
                int k0 = (c + 1) * 16;
                pa0 = *(const float4*)(aptr + (size_t)k0 * TT);
                pa1 = *(const float4*)(aptr + (size_t)(k0 + 8) * TT);
                pb0 = *(const float4*)(bptr + (size_t)k0 * NN);
                pb1 = *(const float4*)(bptr + (size_t)(k0 + 8) * NN);
            }
            int buf = c & 1;
#pragma unroll
            for (int k = 0; k < 16; ++k) {
                float4 a0 = *(const float4*)&PA(buf, k, mr);
                float4 a1 = *(const float4*)&PA(buf, k, mr + 4);
                F4U b0u, b1u;
                b0u.v = *(const float4*)&PB(buf, k, nr);
                b1u.v = *(const float4*)&PB(buf, k, nr + 4);
                float av[8] = {a0.x, a0.y, a0.z, a0.w, a1.x, a1.y, a1.z, a1.w};
                ull bp[4] = {b0u.u[0], b0u.u[1], b1u.u[0], b1u.u[1]};
#pragma unroll
                for (int r = 0; r < 8; ++r) {
                    ull ad = dup2(av[r]);
#pragma unroll
                    for (int p = 0; p < 4; ++p) acc[r][p] = ffma2(ad, bp[p], acc[r][p]);
                }
            }
            if (c + 1 < 8) {
                int nbuf = (c + 1) & 1;
                *(float4*)&PA(nbuf, kb, nb) = pa0;
                *(float4*)&PA(nbuf, kb + 8, nb) = pa1;
                *(float4*)&PB(nbuf, kb, nb) = pb0;
                *(float4*)&PB(nbuf, kb + 8, nb) = pb1;
                __syncthreads();
            }
        }

#pragma unroll
        for (int r = 0; r < 8; ++r) {
            int t = mr + r;
            float bt = __ldg(&b1[t]);
            float o[8];
            unpk(acc[r][0], o[0], o[1]);
            unpk(acc[r][1], o[2], o[3]);
            unpk(acc[r][2], o[4], o[5]);
            unpk(acc[r][3], o[6], o[7]);
            float* op = g_preT + (size_t)b * (TT * NN) + (size_t)t * NN + nr;
            float4 o0 = {o[0] + bt, o[1] + bt, o[2] + bt, o[3] + bt};
            float4 o1 = {o[4] + bt, o[5] + bt, o[6] + bt, o[7] + bt};
            *(float4*)&op[0] = o0;
            *(float4*)&op[4] = o1;
        }
#undef PA
#undef PB
    }
}

// ---------------------------------------------------------------------------
// K_rnn9: best measured RNN (376us, profiled). Unchanged.
// ---------------------------------------------------------------------------
__global__ __launch_bounds__(512, 1) void k_rnn9(const float* __restrict__ h0,
                                                 const float* __restrict__ Wh) {
    extern __shared__ float sm[];
    float* sWs = sm;            // [128][256]
    float* sh = sm + 32768;     // [2][256][4]
    float* sred = sh + 2048;    // [256][4]
    int b0 = blockIdx.x * 4;
    int tid = threadIdx.x;
    int j = tid & 255;
    int kh = tid >> 8;

    for (int i = tid; i < 128 * 64; i += 512) {
        int row = i >> 6;
        int c4 = i & 63;
        int gr = (row < 64) ? row : (row + 64);
        ((float4*)sWs)[i] = *(const float4*)&Wh[(size_t)gr * HH + c4 * 4];
    }
    float wr[64];
    {
        const float* wp = Wh + (size_t)(kh * 128 + 64) * HH + j;
#pragma unroll
        for (int c = 0; c < 64; ++c) wr[c] = wp[(size_t)c * HH];
    }
    if (kh == 0) {
        float4 h4;
        h4.x = h0[(size_t)(b0 + 0) * HH + j];
        h4.y = h0[(size_t)(b0 + 1) * HH + j];
        h4.z = h0[(size_t)(b0 + 2) * HH + j];
        h4.w = h0[(size_t)(b0 + 3) * HH + j];
        *(float4*)&sh[j * 4] = h4;
    }
    __syncthreads();

    ull nx01 = 0, nx23 = 0;
    if (kh == 0) {
        const float* xw = g_xW + (size_t)b0 * HH + j;
        nx01 = pack2(xw[0], xw[HH]);
        nx23 = pack2(xw[2 * HH], xw[3 * HH]);
    }

    const float* swj = sWs + j;
    int smbase = kh * 64;
    int hsm = kh * 128;
    int hrg = kh * 128 + 64;

    for (int s = 0; s < TT; ++s) {
        const float* shc = sh + (s & 1) * 1024;
        float* shn = sh + (1 - (s & 1)) * 1024;

        ull a01, a23;
        if (kh == 0) {
            a01 = nx01; a23 = nx23;
            if (s + 1 < TT) {
                const float* xw = g_xW + (size_t)(s + 1) * (BB * HH) + (size_t)b0 * HH + j;
                nx01 = pack2(xw[0], xw[HH]);
                nx23 = pack2(xw[2 * HH], xw[3 * HH]);
            }
        } else {
            a01 = 0; a23 = 0;
        }
        ull c01 = 0, c23 = 0;

#pragma unroll 16
        for (int k = 0; k < 64; ++k) {
            float w = swj[(smbase + k) * 256];
            F4U hu; hu.v = *(const float4*)&shc[(hsm + k) * 4];
            ull wd = dup2(w);
            a01 = ffma2(hu.u[0], wd, a01);
            a23 = ffma2(hu.u[1], wd, a23);
        }
#pragma unroll
        for (int c = 0; c < 64; ++c) {
            ull wd = dup2(wr[c]);
            F4U hu; hu.v = *(const float4*)&shc[(hrg + c) * 4];
            c01 = ffma2(hu.u[0], wd, c01);
            c23 = ffma2(hu.u[1], wd, c23);
        }

        if (kh == 1) {
            F4U r;
            r.u[0] = fadd2(a01, c01);
            r.u[1] = fadd2(a23, c23);
            *(float4*)&sred[j * 4] = r.v;
        }
        __syncthreads();
        if (kh == 0) {
            F4U p; p.v = *(const float4*)&sred[j * 4];
            a01 = fadd2(fadd2(a01, c01), p.u[0]);
            a23 = fadd2(fadd2(a23, c23), p.u[1]);
            float x0, x1, x2, x3;
            unpk(a01, x0, x1);
            unpk(a23, x2, x3);
            float4 h4o = make_float4(tanh_fast(x0), tanh_fast(x1), tanh_fast(x2), tanh_fast(x3));
            *(float4*)&shn[j * 4] = h4o;
            *(float4*)&g_Hs2[((size_t)s * HH + j) * BB + b0] = h4o;
        }
        __syncthreads();
    }
}

// ---------------------------------------------------------------------------
// K_q3: Q[m][t] = Hs-row(m) @ W2 + b2. (unchanged)
// ---------------------------------------------------------------------------
__global__ __launch_bounds__(256, 2) void k_q3(const float* __restrict__ W2,
                                               const float* __restrict__ b2) {
    __shared__ float sA[2][16][132];
    __shared__ float sB[2][16][128];
    int m0 = blockIdx.x * 128;
    int s = m0 >> 9, b0m = m0 & 511;
    int tid = threadIdx.x;

    int kk0 = tid >> 5;
    int mmo = (tid & 31) * 4;
    int kk1 = kk0 + 8;
    const float* aB = g_Hs2 + (size_t)s * HH * BB + b0m + mmo;
    int kb = tid >> 5;
    int nb = (tid & 31) * 4;
    const float* bptr = W2 + (size_t)kb * TT + nb;

    float4 pa0 = *(const float4*)&aB[(size_t)kk0 * BB];
    float4 pa1 = *(const float4*)&aB[(size_t)kk1 * BB];
    float4 pb0 = *(const float4*)(bptr);
    float4 pb1 = *(const float4*)(bptr + 8 * TT);
    *(float4*)&sA[0][kk0][mmo] = pa0;
    *(float4*)&sA[0][kk1][mmo] = pa1;
    *(float4*)&sB[0][kb][nb] = pb0;
    *(float4*)&sB[0][kb + 8][nb] = pb1;
    __syncthreads();

    int ty = tid >> 4, tx = tid & 15;
    int mr = ty * 8, nr = tx * 8;
    ull acc[8][4] = {};

#pragma unroll 2
    for (int c = 0; c < 16; ++c) {
        if (c + 1 < 16) {
            int k0 = (c + 1) * 16;
            pa0 = *(const float4*)&aB[(size_t)(k0 + kk0) * BB];
            pa1 = *(const float4*)&aB[(size_t)(k0 + kk1) * BB];
            pb0 = *(const float4*)(bptr + (size_t)k0 * TT);
            pb1 = *(const float4*)(bptr + (size_t)(k0 + 8) * TT);
        }
        int buf = c & 1;
#pragma unroll
        for (int k = 0; k < 16; ++k) {
            float4 a0 = *(const float4*)&sA[buf][k][mr];
            float4 a1 = *(const float4*)&sA[buf][k][mr + 4];
            F4U b0u, b1u;
            b0u.v = *(const float4*)&sB[buf][k][nr];
            b1u.v = *(const float4*)&sB[buf][k][nr + 4];
            float av[8] = {a0.x, a0.y, a0.z, a0.w, a1.x, a1.y, a1.z, a1.w};
            ull bp[4] = {b0u.u[0], b0u.u[1], b1u.u[0], b1u.u[1]};
#pragma unroll
            for (int r = 0; r < 8; ++r) {
                ull ad = dup2(av[r]);
#pragma unroll
                for (int p = 0; p < 4; ++p) acc[r][p] = ffma2(ad, bp[p], acc[r][p]);
            }
        }
        if (c + 1 < 16) {
            int nbuf = (c + 1) & 1;
            *(float4*)&sA[nbuf][kk0][mmo] = pa0;
            *(float4*)&sA[nbuf][kk1][mmo] = pa1;
            *(float4*)&sB[nbuf][kb][nb] = pb0;
            *(float4*)&sB[nbuf][kb + 8][nb] = pb1;
            __syncthreads();
        }
    }

    float bias[8];
#pragma unroll
    for (int cc = 0; cc < 8; ++cc) bias[cc] = __ldg(&b2[nr + cc]);
#pragma unroll
    for (int r = 0; r < 8; ++r) {
        float o[8];
        unpk(acc[r][0], o[0], o[1]);
        unpk(acc[r][1], o[2], o[3]);
        unpk(acc[r][2], o[4], o[5]);
        unpk(acc[r][3], o[6], o[7]);
        float* op = g_Q + (size_t)(m0 + mr + r) * TT + nr;
        float4 o0 = {o[0] + bias[0], o[1] + bias[1], o[2] + bias[2], o[3] + bias[3]};
        float4 o1 = {o[4] + bias[4], o[5] + bias[5], o[6] + bias[6], o[7] + bias[7]};
        *(float4*)&op[0] = o0;
        *(float4*)&op[4] = o1;
    }
}

// ---------------------------------------------------------------------------
// K_att9: each thread computes TWO s-values per pass so every scalar sP load
// feeds 2 tanh (halves the dominant LSU term: 7 wavefronts per 8 tanh vs
// att8's 12). 4 s per CTA-iteration; 8 iterations; one barrier each.
// sQ[2][4][128], sred[2][4][4]. MUFU should now be the binding pipe.
// ---------------------------------------------------------------------------
__global__ __launch_bounds__(256) void k_att9(const float* __restrict__ data,
                                              const float* __restrict__ Wv,
                                              float* __restrict__ out) {
    extern __shared__ float sm[];
    float* sP = sm;            // [128][128]  sP[t][n]
    float* sQ = sm + 16384;    // [2][4][128]
    float* sWv = sQ + 1024;    // [128]
    float* sred = sWv + 128;   // [2][4][4]
    int b = blockIdx.x >> 2;
    int sq = blockIdx.x & 3;
    int tid = threadIdx.x;

    const float4* gP = (const float4*)(g_preT + (size_t)b * (TT * NN));
    for (int i = tid; i < 4096; i += 256) ((float4*)sP)[i] = gP[i];
    if (tid < 128) sWv[tid] = Wv[tid];

    int n = tid & 127;
    int g = tid >> 7;          // 0/1: which s-pair this thread owns
    int lane = tid & 31;
    int wig = (tid >> 5) & 3;
    int j0 = g * 2;            // iter-local s indices j0, j0+1

    // preload iteration 0's q rows
    {
        int s0 = sq * 32 + j0;
        sQ[j0 * 128 + n] = g_Q[(size_t)s0 * (BB * TT) + b * TT + n];
        sQ[(j0 + 1) * 128 + n] = g_Q[(size_t)(s0 + 1) * (BB * TT) + b * TT + n];
    }
    __syncthreads();

    const float4* wv4 = (const float4*)sWv;

    for (int it = 0; it < 8; ++it) {
        int cur = it & 1;
        int s0 = sq * 32 + it * 4 + j0;

        float qn0 = 0.f, qn1 = 0.f;
        if (it + 1 < 8) {
            qn0 = g_Q[(size_t)(s0 + 4) * (BB * TT) + b * TT + n];
            qn1 = g_Q[(size_t)(s0 + 5) * (BB * TT) + b * TT + n];
        }

        const float4* qa4 = (const float4*)(sQ + cur * 512 + j0 * 128);
        const float4* qb4 = (const float4*)(sQ + cur * 512 + (j0 + 1) * 128);
        float ea0 = 0.f, ea1 = 0.f, eb0 = 0.f, eb1 = 0.f;
#pragma unroll 8
        for (int t4 = 0; t4 < 32; ++t4) {
            float4 wv = wv4[t4];
            float4 qa = qa4[t4];
            float4 qb = qb4[t4];
            int t = t4 * 4;
            float p0 = sP[(t + 0) * 128 + n];
            float p1 = sP[(t + 1) * 128 + n];
            float p2 = sP[(t + 2) * 128 + n];
            float p3 = sP[(t + 3) * 128 + n];
            ea0 += wv.x * tanh_fast(p0 + qa.x);
            eb0 += wv.x * tanh_fast(p0 + qb.x);
            ea1 += wv.y * tanh_fast(p1 + qa.y);
            eb1 += wv.y * tanh_fast(p1 + qb.y);
            ea0 += wv.z * tanh_fast(p2 + qa.z);
            eb0 += wv.z * tanh_fast(p2 + qb.z);
            ea1 += wv.w * tanh_fast(p3 + qa.w);
            eb1 += wv.w * tanh_fast(p3 + qb.w);
        }
        float exa = __expf(ea0 + ea1);
        float exb = __expf(eb0 + eb1);
        float sa = exa, sb = exb;
#pragma unroll
        for (int o = 16; o; o >>= 1) {
            sa += __shfl_xor_sync(0xFFFFFFFFu, sa, o);
            sb += __shfl_xor_sync(0xFFFFFFFFu, sb, o);
        }
        if (lane == 0) {
            sred[cur * 16 + j0 * 4 + wig] = sa;
            sred[cur * 16 + (j0 + 1) * 4 + wig] = sb;
        }
        if (it + 1 < 8) {
            sQ[(cur ^ 1) * 512 + j0 * 128 + n] = qn0;
            sQ[(cur ^ 1) * 512 + (j0 + 1) * 128 + n] = qn1;
        }
        __syncthreads();  // single barrier per iteration

        const float* ra = sred + cur * 16 + j0 * 4;
        sa = ra[0] + ra[1] + ra[2] + ra[3];
        sb = ra[4] + ra[5] + ra[6] + ra[7];
        float alA = exa / sa;
        float alB = exb / sb;

        int tp = b & 127;
        int bp0 = 4 * s0 + (b >> 7);
        size_t idx0 = (size_t)bp0 * (TT * NN) + tp * NN + n;
        out[idx0] = data[idx0] * alA;
        int bp1 = 4 * (s0 + 1) + (b >> 7);
        size_t idx1 = (size_t)bp1 * (TT * NN) + tp * NN + n;
        out[idx1] = data[idx1] * alB;
    }
}

// ---------------------------------------------------------------------------
extern "C" void kernel_launch(void* const* d_in, const int* in_sizes, int n_in,
                              void* d_out, int out_size) {
    const float* data = (const float*)d_in[0];
    const float* h0 = (const float*)d_in[1];
    const float* Wx = (const float*)d_in[2];
    const float* Wh = (const float*)d_in[3];
    const float* bvec = (const float*)d_in[4];
    const float* W1 = (const float*)d_in[5];
    const float* b1 = (const float*)d_in[6];
    const float* W2 = (const float*)d_in[7];
    const float* b2 = (const float*)d_in[8];
    const float* Wv = (const float*)d_in[9];
    float* out = (float*)d_out;

    const int SM_RNN = (32768 + 2048 + 1024) * 4;      // 140 KB
    const int SM_ATT = (16384 + 1024 + 128 + 32) * 4;  // 70,272 B

    cudaFuncSetAttribute(k_rnn9, cudaFuncAttributeMaxDynamicSharedMemorySize, SM_RNN);
    cudaFuncSetAttribute(k_att9, cudaFuncAttributeMaxDynamicSharedMemorySize, SM_ATT);

    k_xwpre<<<1536, 256>>>(data, Wx, bvec, W1, b1);
    k_rnn9<<<BB / 4, 512, SM_RNN>>>(h0, Wh);
    k_q3<<<(TT * BB) / 128, 256>>>(W2, b2);
    k_att9<<<BB * 4, 256, SM_ATT>>>(data, Wv, out);
}